// round 11
// baseline (speedup 1.0000x reference)
#include <cuda_runtime.h>
#include <cstddef>

// Problem constants
#define BB    4096
#define NXD   64
#define NUD   16
#define HH    50
#define HIDD  256
#define ZD    80
#define W1STRIDE 260
#define W2STRIDE 260

// Output layout
#define OFF_U      0
#define OFF_XTRAJ  (BB*NUD)
#define OFF_XPRED  (OFF_XTRAJ + BB*(HH+1)*NXD)
#define OFF_GX     (OFF_XPRED + BB*HH*NXD)
#define OFF_GU     (OFF_GX + BB*HH*NXD)

// smem layout (float offsets). Total 57,920 floats = 231,680 B
#define SM_W1    0                       // [80][260]
#define SM_W2T   (SM_W1 + ZD*W1STRIDE)   // [64][260]
#define SM_XD    (SM_W2T + NXD*W2STRIDE) // float2 [32 rows][64]
#define SM_TALL  (SM_XD + 32*64*2)       // float  [32 rows][256] t (u staging aliased)
#define SM_GALL  (SM_TALL + 32*256)      // float  [32 rows][256] gh fp32
#define SM_TOTAL_F (SM_GALL + 32*256)

typedef unsigned long long ull;

__device__ float g_u9[BB * HH * NUD];

union F2U { ull u; float2 f; };

__device__ __forceinline__ ull fma2(ull a, ull b, ull c) {
    ull d;
    asm("fma.rn.f32x2 %0, %1, %2, %3;" : "=l"(d) : "l"(a), "l"(b), "l"(c));
    return d;
}
__device__ __forceinline__ ull mul2(ull a, ull b) {
    ull d;
    asm("mul.rn.f32x2 %0, %1, %2;" : "=l"(d) : "l"(a), "l"(b));
    return d;
}
// tanh(x) = 1 - 2/(exp2(2*log2e*x)+1)
__device__ __forceinline__ float tanhfast(float x) {
    float e, r;
    asm("ex2.approx.f32 %0, %1;" : "=f"(e) : "f"(x * 2.885390081777927f));
    asm("rcp.approx.f32 %0, %1;" : "=f"(r) : "f"(e + 1.0f));
    return fmaf(-2.0f, r, 1.0f);
}

// ---------------------------------------------------------------------------
__global__ void prep_kernel(const float* __restrict__ noise,
                            const int* __restrict__ nit_p,
                            float* __restrict__ out_u) {
    const int TOT = BB * HH * NUD;
    int idx = blockIdx.x * blockDim.x + threadIdx.x;
    if (idx >= TOT) return;
    int nit = *nit_p;
    float s = 0.f;
    for (int it = 0; it < nit - 1; ++it)
        s += noise[(size_t)it * TOT + idx];
    float u9 = 0.001f * s;
    g_u9[idx] = u9;
    int rem = idx % (HH * NUD);
    if (rem < NUD) {
        float u10 = u9 + 0.001f * noise[(size_t)(nit - 1) * TOT + idx];
        int b = idx / (HH * NUD);
        out_u[b * NUD + rem] = u10;
    }
}

// ---------------------------------------------------------------------------
// GEMV2 for 4 rows: x_next = x + 0.1 * t @ W2; writes xd + globals.
// step = the step being finalized (produces x_{step+1}).
// ---------------------------------------------------------------------------
__device__ __forceinline__ void gemv2_half(
    int step, int b0r, int lrr, int lane,
    const float* __restrict__ tall, float2* __restrict__ xd,
    const ulonglong2* __restrict__ w2a, const ulonglong2* __restrict__ w2b,
    float* __restrict__ out_xtraj, float* __restrict__ out_xpred)
{
    ull acc[4][2];
    #pragma unroll
    for (int r = 0; r < 4; ++r) { acc[r][0] = 0ull; acc[r][1] = 0ull; }
    #pragma unroll 4
    for (int q = 0; q < HIDD / 4; ++q) {
        ulonglong2 wa = w2a[q];
        ulonglong2 wb = w2b[q];
        #pragma unroll
        for (int r = 0; r < 4; ++r) {
            ulonglong2 tv = *(const ulonglong2*)&tall[(lrr + r) * 256 + 4 * q];
            acc[r][0] = fma2(tv.x, wa.x, acc[r][0]);
            acc[r][0] = fma2(tv.y, wa.y, acc[r][0]);
            acc[r][1] = fma2(tv.x, wb.x, acc[r][1]);
            acc[r][1] = fma2(tv.y, wb.y, acc[r][1]);
        }
    }
    #pragma unroll
    for (int r = 0; r < 4; ++r) {
        int b = b0r + r;
        F2U a0; a0.u = acc[r][0];
        F2U a1; a1.u = acc[r][1];
        float xn0 = xd[(lrr + r) * 64 + lane].x      + 0.1f * (a0.f.x + a0.f.y);
        float xn1 = xd[(lrr + r) * 64 + 32 + lane].x + 0.1f * (a1.f.x + a1.f.y);
        size_t base_t = (size_t)b * (HH + 1) * NXD + (size_t)(step + 1) * NXD;
        size_t base_p = (size_t)b * HH * NXD + (size_t)step * NXD;
        out_xtraj[base_t + lane]      = xn0;
        out_xtraj[base_t + 32 + lane] = xn1;
        out_xpred[base_p + lane]      = xn0;
        out_xpred[base_p + 32 + lane] = xn1;
        xd[(lrr + r) * 64 + lane]      = make_float2(xn0, xn0);
        xd[(lrr + r) * 64 + 32 + lane] = make_float2(xn1, xn1);
    }
}

// ---------------------------------------------------------------------------
// gx/gu for 8 rows of step `step` from fp32 gh in gall.
// ---------------------------------------------------------------------------
__device__ __forceinline__ void grad_compute(
    int step, int b0, int lr, int lane, int ui, bool lo16,
    const float* __restrict__ gall,
    const ulonglong2* __restrict__ wia, const ulonglong2* __restrict__ wib,
    const ulonglong2* __restrict__ wic,
    float* __restrict__ out_gx, float* __restrict__ out_gu)
{
    const float* gb_ = gall + lr * 256;
    ull ga[8], gb[8], gc4[4];
    #pragma unroll
    for (int r = 0; r < 8; ++r) { ga[r] = 0ull; gb[r] = 0ull; }
    #pragma unroll
    for (int r = 0; r < 4; ++r) gc4[r] = 0ull;

    #pragma unroll 4
    for (int q = 0; q < HIDD / 4; ++q) {
        ulonglong2 wa = wia[q];
        ulonglong2 wb = wib[q];
        ulonglong2 wc = wic[q];
        ull gl[8][2];
        #pragma unroll
        for (int r = 0; r < 8; ++r) {
            ulonglong2 gv = *(const ulonglong2*)&gb_[r * 256 + 4 * q];
            gl[r][0] = gv.x; gl[r][1] = gv.y;
            ga[r] = fma2(gv.x, wa.x, ga[r]);
            ga[r] = fma2(gv.y, wa.y, ga[r]);
            gb[r] = fma2(gv.x, wb.x, gb[r]);
            gb[r] = fma2(gv.y, wb.y, gb[r]);
        }
        #pragma unroll
        for (int r = 0; r < 4; ++r) {
            ull s0 = lo16 ? gl[r][0] : gl[r + 4][0];
            ull s1 = lo16 ? gl[r][1] : gl[r + 4][1];
            gc4[r] = fma2(s0, wc.x, gc4[r]);
            gc4[r] = fma2(s1, wc.y, gc4[r]);
        }
    }
    #pragma unroll
    for (int r = 0; r < 8; ++r) {
        int b = b0 + r;
        F2U va; va.u = ga[r];
        F2U vb; vb.u = gb[r];
        size_t base_gx = (size_t)b * HH * NXD + (size_t)step * NXD;
        out_gx[base_gx + lane]      = 1.f + va.f.x + va.f.y;
        out_gx[base_gx + 32 + lane] = 1.f + vb.f.x + vb.f.y;
    }
    #pragma unroll
    for (int r = 0; r < 4; ++r) {
        int b = b0 + r + (lo16 ? 0 : 4);
        F2U vc; vc.u = gc4[r];
        out_gu[(size_t)b * HH * NUD + (size_t)step * NUD + ui] =
            vc.f.x + vc.f.y;
    }
}

// ---------------------------------------------------------------------------
// grid 128 x 256 threads. Warps 0-3: rollout (GEMV1+tanh for 8 rows, GEMV2
// for rows 0-3). Warps 4-7: GEMV2 for rows 4-7 (eager) + gx/gu (lagged one
// step, overlapping GEMV1). 3 barriers/step keep both roles feeding the fma
// pipe in every segment.
// ---------------------------------------------------------------------------
__global__ __launch_bounds__(256, 1)
void mpc_kernel(const float* __restrict__ x0,
                const float* __restrict__ W1g,   // [80,256]
                const float* __restrict__ b1g,   // [256]
                const float* __restrict__ W2g,   // [256,64]
                float* __restrict__ out_xtraj,
                float* __restrict__ out_xpred,
                float* __restrict__ out_gx,
                float* __restrict__ out_gu) {
    extern __shared__ float smem[];
    float*  W1s  = smem + SM_W1;
    float*  W2Ts = smem + SM_W2T;
    float2* xd   = (float2*)(smem + SM_XD);
    float*  tall = smem + SM_TALL;
    float*  gall = smem + SM_GALL;

    const int tid = threadIdx.x;

    // ---- Stage weights + c2 scratch (parked in tall[0..255]) ----
    for (int idx = tid; idx < ZD * HIDD; idx += 256) {
        int i = idx >> 8, m = idx & 255;
        W1s[i * W1STRIDE + m] = W1g[idx];
    }
    for (int idx = tid; idx < HIDD * NXD; idx += 256) {
        int m = idx >> 6, j = idx & 63;
        W2Ts[j * W2STRIDE + m] = W2g[idx];
    }
    {
        int m = tid;
        float s = 0.f;
        #pragma unroll 8
        for (int j = 0; j < NXD; ++j) s += W2g[m * NXD + j];
        tall[m] = 0.1f * s;   // c2 scratch
    }
    __syncthreads();

    const int  w    = tid >> 5, lane = tid & 31;
    const int  wl   = w & 3;
    const bool roll = (w < 4);
    const int  lr   = wl * 8;
    const int  b0   = blockIdx.x * 32 + lr;
    const int  m2   = 2 * lane;
    const int  urh  = lane >> 4, ui = lane & 15;
    const bool lo16 = (lane < 16);

    ull b1p[4], c2p[4], nc2p[4];
    float up[4];
    if (roll) {
        #pragma unroll
        for (int j = 0; j < 4; ++j) {
            b1p[j] = *(const ull*)&b1g[64 * j + m2];
            F2U c; c.u = *(const ull*)&tall[64 * j + m2];
            c2p[j] = c.u;
            F2U n; n.f.x = -c.f.x; n.f.y = -c.f.y;
            nc2p[j] = n.u;
        }
        #pragma unroll
        for (int r = 0; r < 8; ++r) {
            int b = b0 + r;
            float xa = x0[b * NXD + lane];
            float xb = x0[b * NXD + 32 + lane];
            xd[(lr + r) * 64 + lane]      = make_float2(xa, xa);
            xd[(lr + r) * 64 + 32 + lane] = make_float2(xb, xb);
            size_t base = (size_t)b * (HH + 1) * NXD;
            out_xtraj[base + lane]      = xa;
            out_xtraj[base + 32 + lane] = xb;
        }
        #pragma unroll
        for (int v = 0; v < 4; ++v)
            up[v] = g_u9[(size_t)(b0 + 2 * v + urh) * HH * NUD + ui];
    }
    __syncthreads();   // c2 scratch consumed; xd initialized; tall free

    if (roll) {
        // u staging aliases THIS warp's own tall row lr (dead between uses)
        float2* ud = (float2*)(tall + lr * 256);   // [8 rows][16] float2
        const ulonglong2* w2a = (const ulonglong2*)&W2Ts[lane * W2STRIDE];
        const ulonglong2* w2b = (const ulonglong2*)&W2Ts[(lane + 32) * W2STRIDE];

        for (int k = 0; k < HH; ++k) {
            // ---- seg1: finalize step k-1 for rows 0-3 ----
            if (k > 0)
                gemv2_half(k - 1, b0, lr, lane, tall, xd, w2a, w2b,
                           out_xtraj, out_xpred);
            __syncthreads();   // C: grad's xd rows 4-7 ready; t/ud reuse safe

            // ---- seg2: stage controls + GEMV1(k) ----
            #pragma unroll
            for (int v = 0; v < 4; ++v)
                ud[(2 * v + urh) * 16 + ui] = make_float2(up[v], up[v]);
            __syncwarp();
            if (k + 1 < HH) {
                #pragma unroll
                for (int v = 0; v < 4; ++v)
                    up[v] = g_u9[(size_t)(b0 + 2 * v + urh) * HH * NUD
                                 + (k + 1) * NUD + ui];
            }

            ull h[8][4];
            #pragma unroll
            for (int r = 0; r < 8; ++r)
                #pragma unroll
                for (int j = 0; j < 4; ++j) h[r][j] = b1p[j];

            #pragma unroll 2
            for (int i = 0; i < NXD; i += 2) {       // x part
                const float* wr0 = &W1s[i * W1STRIDE];
                const float* wr1 = &W1s[(i + 1) * W1STRIDE];
                ull a0 = *(const ull*)&wr0[m2];
                ull a1 = *(const ull*)&wr0[m2 + 64];
                ull a2 = *(const ull*)&wr0[m2 + 128];
                ull a3 = *(const ull*)&wr0[m2 + 192];
                ull c0 = *(const ull*)&wr1[m2];
                ull c1 = *(const ull*)&wr1[m2 + 64];
                ull c2_ = *(const ull*)&wr1[m2 + 128];
                ull c3 = *(const ull*)&wr1[m2 + 192];
                #pragma unroll
                for (int r = 0; r < 8; ++r) {
                    ulonglong2 z2 = *(const ulonglong2*)&xd[(lr + r) * 64 + i];
                    h[r][0] = fma2(z2.x, a0, h[r][0]);
                    h[r][1] = fma2(z2.x, a1, h[r][1]);
                    h[r][2] = fma2(z2.x, a2, h[r][2]);
                    h[r][3] = fma2(z2.x, a3, h[r][3]);
                    h[r][0] = fma2(z2.y, c0, h[r][0]);
                    h[r][1] = fma2(z2.y, c1, h[r][1]);
                    h[r][2] = fma2(z2.y, c2_, h[r][2]);
                    h[r][3] = fma2(z2.y, c3, h[r][3]);
                }
            }
            #pragma unroll 2
            for (int i = NXD; i < ZD; i += 2) {      // u part
                const float* wr0 = &W1s[i * W1STRIDE];
                const float* wr1 = &W1s[(i + 1) * W1STRIDE];
                ull a0 = *(const ull*)&wr0[m2];
                ull a1 = *(const ull*)&wr0[m2 + 64];
                ull a2 = *(const ull*)&wr0[m2 + 128];
                ull a3 = *(const ull*)&wr0[m2 + 192];
                ull c0 = *(const ull*)&wr1[m2];
                ull c1 = *(const ull*)&wr1[m2 + 64];
                ull c2_ = *(const ull*)&wr1[m2 + 128];
                ull c3 = *(const ull*)&wr1[m2 + 192];
                #pragma unroll
                for (int r = 0; r < 8; ++r) {
                    ulonglong2 z2 = *(const ulonglong2*)&ud[r * 16 + (i - NXD)];
                    h[r][0] = fma2(z2.x, a0, h[r][0]);
                    h[r][1] = fma2(z2.x, a1, h[r][1]);
                    h[r][2] = fma2(z2.x, a2, h[r][2]);
                    h[r][3] = fma2(z2.x, a3, h[r][3]);
                    h[r][0] = fma2(z2.y, c0, h[r][0]);
                    h[r][1] = fma2(z2.y, c1, h[r][1]);
                    h[r][2] = fma2(z2.y, c2_, h[r][2]);
                    h[r][3] = fma2(z2.y, c3, h[r][3]);
                }
            }

            __syncthreads();   // A: grad done reading gh(k-1)

            // ---- seg3: tanh; stage t (f32) and gh (f32) ----
            #pragma unroll
            for (int r = 0; r < 8; ++r)
                #pragma unroll
                for (int j = 0; j < 4; ++j) {
                    F2U hv; hv.u = h[r][j];
                    F2U tv;
                    tv.f.x = tanhfast(hv.f.x);
                    tv.f.y = tanhfast(hv.f.y);
                    *(ull*)&tall[(lr + r) * 256 + 64 * j + m2] = tv.u;
                    ull gh = fma2(mul2(tv.u, tv.u), nc2p[j], c2p[j]);
                    *(ull*)&gall[(lr + r) * 256 + 64 * j + m2] = gh;
                }

            __syncthreads();   // B: t(k), gh(k) ready
        }
        // epilogue: finalize last step, rows 0-3
        gemv2_half(HH - 1, b0, lr, lane, tall, xd, w2a, w2b,
                   out_xtraj, out_xpred);
    } else {
        // ---------------- helper warps ----------------
        const ulonglong2* w2a = (const ulonglong2*)&W2Ts[lane * W2STRIDE];
        const ulonglong2* w2b = (const ulonglong2*)&W2Ts[(lane + 32) * W2STRIDE];
        const ulonglong2* wia = (const ulonglong2*)&W1s[lane * W1STRIDE];
        const ulonglong2* wib = (const ulonglong2*)&W1s[(32 + lane) * W1STRIDE];
        const ulonglong2* wic = (const ulonglong2*)&W1s[(64 + ui) * W1STRIDE];

        for (int k = 0; k < HH; ++k) {
            // ---- seg1: finalize step k-1 for rows 4-7 ----
            if (k > 0)
                gemv2_half(k - 1, b0 + 4, lr + 4, lane, tall, xd, w2a, w2b,
                           out_xtraj, out_xpred);
            __syncthreads();   // C

            // ---- seg2: gx/gu for step k-1 (overlaps roll's GEMV1) ----
            if (k > 0)
                grad_compute(k - 1, b0, lr, lane, ui, lo16, gall,
                             wia, wib, wic, out_gx, out_gu);
            __syncthreads();   // A
            __syncthreads();   // B
        }
        // epilogue: finalize last step, rows 4-7, then its gx/gu
        gemv2_half(HH - 1, b0 + 4, lr + 4, lane, tall, xd, w2a, w2b,
                   out_xtraj, out_xpred);
        grad_compute(HH - 1, b0, lr, lane, ui, lo16, gall,
                     wia, wib, wic, out_gx, out_gu);
    }
}

// ---------------------------------------------------------------------------
extern "C" void kernel_launch(void* const* d_in, const int* in_sizes, int n_in,
                              void* d_out, int out_size) {
    const float* x0    = (const float*)d_in[0];
    const float* W1    = (const float*)d_in[2];
    const float* b1    = (const float*)d_in[3];
    const float* W2    = (const float*)d_in[4];
    const float* noise = (const float*)d_in[5];
    const int*   nit   = (const int*)d_in[6];

    float* out = (float*)d_out;
    float* out_u     = out + OFF_U;
    float* out_xtraj = out + OFF_XTRAJ;
    float* out_xpred = out + OFF_XPRED;
    float* out_gx    = out + OFF_GX;
    float* out_gu    = out + OFF_GU;

    {
        int tot = BB * HH * NUD;
        prep_kernel<<<(tot + 255) / 256, 256>>>(noise, nit, out_u);
    }

    const size_t smem_bytes = (size_t)SM_TOTAL_F * sizeof(float);  // 231,680
    cudaFuncSetAttribute(mpc_kernel,
                         cudaFuncAttributeMaxDynamicSharedMemorySize,
                         (int)smem_bytes);
    mpc_kernel<<<BB / 32, 256, smem_bytes>>>(x0, W1, b1, W2,
                                             out_xtraj, out_xpred,
                                             out_gx, out_gu);
}

// round 12
// speedup vs baseline: 1.0437x; 1.0437x over previous
#include <cuda_runtime.h>
#include <cstddef>

// Problem constants
#define BB    4096
#define NXD   64
#define NUD   16
#define HH    50
#define HIDD  256
#define ZD    80
#define W1STRIDE 260
#define W2STRIDE 260

// Output layout
#define OFF_U      0
#define OFF_XTRAJ  (BB*NUD)
#define OFF_XPRED  (OFF_XTRAJ + BB*(HH+1)*NXD)
#define OFF_GX     (OFF_XPRED + BB*HH*NXD)
#define OFF_GU     (OFF_GX + BB*HH*NXD)

// smem layout (float offsets). Total 56,896 floats = 227,584 B (<= 232,448)
#define SM_W1    0                        // [80][260]
#define SM_W2T   (SM_W1 + ZD*W1STRIDE)    // [64][260]
#define SM_ZP    (SM_W2T + NXD*W2STRIDE)  // float [32 rows][80]  z = [x | u], plain
#define SM_TALL  (SM_ZP + 32*ZD)          // float [32 rows][256] t
#define SM_GALL  (SM_TALL + 32*256)       // float [32 rows][256] gh fp32
#define SM_B1    (SM_GALL + 32*256)       // [256]
#define SM_C2    (SM_B1 + 256)            // [256]
#define SM_TOTAL_F (SM_C2 + 256)

#define NT 384   // 12 warps: 4 roll (8 rows each) + 8 grad (4 rows each)

typedef unsigned long long ull;

__device__ float g_u9[BB * HH * NUD];

union F2U { ull u; float2 f; };

__device__ __forceinline__ ull fma2(ull a, ull b, ull c) {
    ull d;
    asm("fma.rn.f32x2 %0, %1, %2, %3;" : "=l"(d) : "l"(a), "l"(b), "l"(c));
    return d;
}
__device__ __forceinline__ ull mul2(ull a, ull b) {
    ull d;
    asm("mul.rn.f32x2 %0, %1, %2;" : "=l"(d) : "l"(a), "l"(b));
    return d;
}
// tanh(x) = 1 - 2/(exp2(2*log2e*x)+1)
__device__ __forceinline__ float tanhfast(float x) {
    float e, r;
    asm("ex2.approx.f32 %0, %1;" : "=f"(e) : "f"(x * 2.885390081777927f));
    asm("rcp.approx.f32 %0, %1;" : "=f"(r) : "f"(e + 1.0f));
    return fmaf(-2.0f, r, 1.0f);
}
__device__ __forceinline__ ull dup2(float v) {
    F2U p; p.f.x = v; p.f.y = v; return p.u;
}

// ---------------------------------------------------------------------------
__global__ void prep_kernel(const float* __restrict__ noise,
                            const int* __restrict__ nit_p,
                            float* __restrict__ out_u) {
    const int TOT = BB * HH * NUD;
    int idx = blockIdx.x * blockDim.x + threadIdx.x;
    if (idx >= TOT) return;
    int nit = *nit_p;
    float s = 0.f;
    for (int it = 0; it < nit - 1; ++it)
        s += noise[(size_t)it * TOT + idx];
    float u9 = 0.001f * s;
    g_u9[idx] = u9;
    int rem = idx % (HH * NUD);
    if (rem < NUD) {
        float u10 = u9 + 0.001f * noise[(size_t)(nit - 1) * TOT + idx];
        int b = idx / (HH * NUD);
        out_u[b * NUD + rem] = u10;
    }
}

// ---------------------------------------------------------------------------
// grid 128 x 384. Warps 0-3: rollout (8 rows each; GEMV1 in 2 m-halves +
// tanh + GEMV2). Warps 4-11: grad, 4 rows each (two grad warps per roll
// warp's row block), lagging via the fp32 gh buffer. 2 barriers/step:
//   A (inside half0, before gh writes): grad done reading gh(k-1)
//   B (after both halves staged):       gh(k)/t(k) ready
// ---------------------------------------------------------------------------
__global__ __launch_bounds__(NT, 1)
void mpc_kernel(const float* __restrict__ x0,
                const float* __restrict__ W1g,   // [80,256]
                const float* __restrict__ b1g,   // [256]
                const float* __restrict__ W2g,   // [256,64]
                float* __restrict__ out_xtraj,
                float* __restrict__ out_xpred,
                float* __restrict__ out_gx,
                float* __restrict__ out_gu) {
    extern __shared__ float smem[];
    float* W1s  = smem + SM_W1;
    float* W2Ts = smem + SM_W2T;
    float* zp   = smem + SM_ZP;
    float* tall = smem + SM_TALL;
    float* gall = smem + SM_GALL;
    float* b1s  = smem + SM_B1;
    float* c2s  = smem + SM_C2;

    const int tid = threadIdx.x;

    // ---- Stage weights, b1, c2 ----
    for (int idx = tid; idx < ZD * HIDD; idx += NT) {
        int i = idx >> 8, m = idx & 255;
        W1s[i * W1STRIDE + m] = W1g[idx];
    }
    for (int idx = tid; idx < HIDD * NXD; idx += NT) {
        int m = idx >> 6, j = idx & 63;
        W2Ts[j * W2STRIDE + m] = W2g[idx];
    }
    if (tid < HIDD) {
        int m = tid;
        float s = 0.f;
        #pragma unroll 8
        for (int j = 0; j < NXD; ++j) s += W2g[m * NXD + j];
        c2s[m] = 0.1f * s;
        b1s[m] = b1g[m];
    }
    __syncthreads();

    const int  w    = tid >> 5, lane = tid & 31;
    const bool roll = (w < 4);
    const int  m2   = 2 * lane;
    const int  urh  = lane >> 4, ui = lane & 15;
    const bool lo16 = (lane < 16);

    if (roll) {
        const int lr = w * 8;
        const int b0 = blockIdx.x * 32 + lr;

        // init x into zp (plain) + x_traj[:,0,:]
        #pragma unroll
        for (int r = 0; r < 8; ++r) {
            int b = b0 + r;
            float xa = x0[b * NXD + lane];
            float xb = x0[b * NXD + 32 + lane];
            zp[(lr + r) * ZD + lane]      = xa;
            zp[(lr + r) * ZD + 32 + lane] = xb;
            size_t base = (size_t)b * (HH + 1) * NXD;
            out_xtraj[base + lane]      = xa;
            out_xtraj[base + 32 + lane] = xb;
        }
        float up[4];
        #pragma unroll
        for (int v = 0; v < 4; ++v)
            up[v] = g_u9[(size_t)(b0 + 2 * v + urh) * HH * NUD + ui];

        const ulonglong2* w2a = (const ulonglong2*)&W2Ts[lane * W2STRIDE];
        const ulonglong2* w2b = (const ulonglong2*)&W2Ts[(lane + 32) * W2STRIDE];

        for (int k = 0; k < HH; ++k) {
            // ---- stage controls (plain) ----
            #pragma unroll
            for (int v = 0; v < 4; ++v)
                zp[(lr + 2 * v + urh) * ZD + NXD + ui] = up[v];
            __syncwarp();
            if (k + 1 < HH) {
                #pragma unroll
                for (int v = 0; v < 4; ++v)
                    up[v] = g_u9[(size_t)(b0 + 2 * v + urh) * HH * NUD
                                 + (k + 1) * NUD + ui];
            }

            // ---- GEMV1 in 2 m-halves of 128 ----
            #pragma unroll
            for (int half = 0; half < 2; ++half) {
                const int mo = 128 * half;
                ull h[8][2];
                {
                    ull bp0 = *(const ull*)&b1s[mo + m2];
                    ull bp1 = *(const ull*)&b1s[mo + 64 + m2];
                    #pragma unroll
                    for (int r = 0; r < 8; ++r) { h[r][0] = bp0; h[r][1] = bp1; }
                }
                #pragma unroll 4
                for (int i = 0; i < ZD; i += 2) {
                    const float* wr0 = &W1s[i * W1STRIDE + mo];
                    const float* wr1 = &W1s[(i + 1) * W1STRIDE + mo];
                    ull a0 = *(const ull*)&wr0[m2];
                    ull a1 = *(const ull*)&wr0[m2 + 64];
                    ull c0 = *(const ull*)&wr1[m2];
                    ull c1 = *(const ull*)&wr1[m2 + 64];
                    #pragma unroll
                    for (int r = 0; r < 8; ++r) {
                        float2 zv = *(const float2*)&zp[(lr + r) * ZD + i];
                        ull p0 = dup2(zv.x);
                        ull p1 = dup2(zv.y);
                        h[r][0] = fma2(p0, a0, h[r][0]);
                        h[r][1] = fma2(p0, a1, h[r][1]);
                        h[r][0] = fma2(p1, c0, h[r][0]);
                        h[r][1] = fma2(p1, c1, h[r][1]);
                    }
                }

                if (half == 0) __syncthreads();   // A: grad done with gh(k-1)

                // tanh + stage t and gh for this half
                F2U c20; c20.u = *(const ull*)&c2s[mo + m2];
                F2U c21; c21.u = *(const ull*)&c2s[mo + 64 + m2];
                F2U n0;  n0.f.x = -c20.f.x; n0.f.y = -c20.f.y;
                F2U n1;  n1.f.x = -c21.f.x; n1.f.y = -c21.f.y;
                #pragma unroll
                for (int r = 0; r < 8; ++r) {
                    #pragma unroll
                    for (int j = 0; j < 2; ++j) {
                        F2U hv; hv.u = h[r][j];
                        F2U tv;
                        tv.f.x = tanhfast(hv.f.x);
                        tv.f.y = tanhfast(hv.f.y);
                        int off = (lr + r) * 256 + mo + 64 * j + m2;
                        *(ull*)&tall[off] = tv.u;
                        ull gh = fma2(mul2(tv.u, tv.u),
                                      j ? n1.u : n0.u,
                                      j ? c21.u : c20.u);
                        *(ull*)&gall[off] = gh;
                    }
                }
            }

            __syncthreads();   // B: t(k), gh(k) ready

            // ---- GEMV2: x_next = x + 0.1 * t @ W2 (8 rows) ----
            ull acc[8][2];
            #pragma unroll
            for (int r = 0; r < 8; ++r) { acc[r][0] = 0ull; acc[r][1] = 0ull; }
            #pragma unroll 4
            for (int q = 0; q < HIDD / 4; ++q) {
                ulonglong2 wa = w2a[q];
                ulonglong2 wb = w2b[q];
                #pragma unroll
                for (int r = 0; r < 8; ++r) {
                    ulonglong2 tv =
                        *(const ulonglong2*)&tall[(lr + r) * 256 + 4 * q];
                    acc[r][0] = fma2(tv.x, wa.x, acc[r][0]);
                    acc[r][0] = fma2(tv.y, wa.y, acc[r][0]);
                    acc[r][1] = fma2(tv.x, wb.x, acc[r][1]);
                    acc[r][1] = fma2(tv.y, wb.y, acc[r][1]);
                }
            }
            #pragma unroll
            for (int r = 0; r < 8; ++r) {
                int b = b0 + r;
                F2U a0; a0.u = acc[r][0];
                F2U a1; a1.u = acc[r][1];
                float xn0 = zp[(lr + r) * ZD + lane]
                            + 0.1f * (a0.f.x + a0.f.y);
                float xn1 = zp[(lr + r) * ZD + 32 + lane]
                            + 0.1f * (a1.f.x + a1.f.y);
                size_t base_t = (size_t)b * (HH + 1) * NXD
                                + (size_t)(k + 1) * NXD;
                size_t base_p = (size_t)b * HH * NXD + (size_t)k * NXD;
                out_xtraj[base_t + lane]      = xn0;
                out_xtraj[base_t + 32 + lane] = xn1;
                out_xpred[base_p + lane]      = xn0;
                out_xpred[base_p + 32 + lane] = xn1;
                zp[(lr + r) * ZD + lane]      = xn0;
                zp[(lr + r) * ZD + 32 + lane] = xn1;
            }
            __syncwarp();
        }
    } else {
        // ---------------- grad warps: 4 rows each ----------------
        const int gw  = w - 4;
        const int p   = gw & 3;
        const int hs  = gw >> 2;
        const int lrg = p * 8 + hs * 4;          // local row base (4 rows)
        const int bg  = blockIdx.x * 32 + lrg;

        const ulonglong2* wia = (const ulonglong2*)&W1s[lane * W1STRIDE];
        const ulonglong2* wib = (const ulonglong2*)&W1s[(32 + lane) * W1STRIDE];
        const ulonglong2* wic = (const ulonglong2*)&W1s[(64 + ui) * W1STRIDE];
        const float* gb_ = gall + lrg * 256;

        for (int k = 0; k < HH; ++k) {
            __syncthreads();   // A
            __syncthreads();   // B: gh(k) ready

            ull ga[4], gb4[4], gc2[2];
            #pragma unroll
            for (int r = 0; r < 4; ++r) { ga[r] = 0ull; gb4[r] = 0ull; }
            gc2[0] = 0ull; gc2[1] = 0ull;

            #pragma unroll 4
            for (int q = 0; q < HIDD / 4; ++q) {
                ulonglong2 wa = wia[q];
                ulonglong2 wb = wib[q];
                ulonglong2 wc = wic[q];
                ull gl[4][2];
                #pragma unroll
                for (int r = 0; r < 4; ++r) {
                    ulonglong2 gv = *(const ulonglong2*)&gb_[r * 256 + 4 * q];
                    gl[r][0] = gv.x; gl[r][1] = gv.y;
                    ga[r]  = fma2(gv.x, wa.x, ga[r]);
                    ga[r]  = fma2(gv.y, wa.y, ga[r]);
                    gb4[r] = fma2(gv.x, wb.x, gb4[r]);
                    gb4[r] = fma2(gv.y, wb.y, gb4[r]);
                }
                #pragma unroll
                for (int r = 0; r < 2; ++r) {
                    ull s0 = lo16 ? gl[r][0] : gl[r + 2][0];
                    ull s1 = lo16 ? gl[r][1] : gl[r + 2][1];
                    gc2[r] = fma2(s0, wc.x, gc2[r]);
                    gc2[r] = fma2(s1, wc.y, gc2[r]);
                }
            }
            #pragma unroll
            for (int r = 0; r < 4; ++r) {
                int b = bg + r;
                F2U va; va.u = ga[r];
                F2U vb; vb.u = gb4[r];
                size_t base_gx = (size_t)b * HH * NXD + (size_t)k * NXD;
                out_gx[base_gx + lane]      = 1.f + va.f.x + va.f.y;
                out_gx[base_gx + 32 + lane] = 1.f + vb.f.x + vb.f.y;
            }
            #pragma unroll
            for (int r = 0; r < 2; ++r) {
                int b = bg + r + (lo16 ? 0 : 2);
                F2U vc; vc.u = gc2[r];
                out_gu[(size_t)b * HH * NUD + (size_t)k * NUD + ui] =
                    vc.f.x + vc.f.y;
            }
        }
    }
}

// ---------------------------------------------------------------------------
extern "C" void kernel_launch(void* const* d_in, const int* in_sizes, int n_in,
                              void* d_out, int out_size) {
    const float* x0    = (const float*)d_in[0];
    const float* W1    = (const float*)d_in[2];
    const float* b1    = (const float*)d_in[3];
    const float* W2    = (const float*)d_in[4];
    const float* noise = (const float*)d_in[5];
    const int*   nit   = (const int*)d_in[6];

    float* out = (float*)d_out;
    float* out_u     = out + OFF_U;
    float* out_xtraj = out + OFF_XTRAJ;
    float* out_xpred = out + OFF_XPRED;
    float* out_gx    = out + OFF_GX;
    float* out_gu    = out + OFF_GU;

    {
        int tot = BB * HH * NUD;
        prep_kernel<<<(tot + 255) / 256, 256>>>(noise, nit, out_u);
    }

    const size_t smem_bytes = (size_t)SM_TOTAL_F * sizeof(float);  // 227,584
    cudaFuncSetAttribute(mpc_kernel,
                         cudaFuncAttributeMaxDynamicSharedMemorySize,
                         (int)smem_bytes);
    mpc_kernel<<<BB / 32, NT, smem_bytes>>>(x0, W1, b1, W2,
                                            out_xtraj, out_xpred,
                                            out_gx, out_gu);
}

// round 13
// speedup vs baseline: 1.0694x; 1.0246x over previous
#include <cuda_runtime.h>
#include <cstddef>

// Problem constants
#define BB    4096
#define NXD   64
#define NUD   16
#define HH    50
#define HIDD  256
#define ZD    80
#define W1STRIDE 260
#define W2STRIDE 260

// Output layout
#define OFF_U      0
#define OFF_XTRAJ  (BB*NUD)
#define OFF_XPRED  (OFF_XTRAJ + BB*(HH+1)*NXD)
#define OFF_GX     (OFF_XPRED + BB*HH*NXD)
#define OFF_GU     (OFF_GX + BB*HH*NXD)

// smem layout (float offsets). Total 57,920 floats = 231,680 B
#define SM_W1    0                        // [80][260] m-permuted
#define SM_W2T   (SM_W1 + ZD*W1STRIDE)    // [64][260] m-permuted
#define SM_XD    (SM_W2T + NXD*W2STRIDE)  // float2 [32 rows][64] dup x
#define SM_TALL  (SM_XD + 32*64*2)        // float [32 rows][256] t, m-permuted (u alias)
#define SM_GALL  (SM_TALL + 32*256)       // float [32 rows][256] gh fp32, m-permuted
#define SM_TOTAL_F (SM_GALL + 32*256)

#define NT 384   // 12 warps: 8 roll (4 rows each) + 4 grad (8 rows each)

typedef unsigned long long ull;

__device__ float g_u9[BB * HH * NUD];

union F2U { ull u; float2 f; };

__device__ __forceinline__ ull fma2(ull a, ull b, ull c) {
    ull d;
    asm("fma.rn.f32x2 %0, %1, %2, %3;" : "=l"(d) : "l"(a), "l"(b), "l"(c));
    return d;
}
__device__ __forceinline__ ull mul2(ull a, ull b) {
    ull d;
    asm("mul.rn.f32x2 %0, %1, %2;" : "=l"(d) : "l"(a), "l"(b));
    return d;
}
// tanh(x) = 1 - 2/(exp2(2*log2e*x)+1)
__device__ __forceinline__ float tanhfast(float x) {
    float e, r;
    asm("ex2.approx.f32 %0, %1;" : "=f"(e) : "f"(x * 2.885390081777927f));
    asm("rcp.approx.f32 %0, %1;" : "=f"(r) : "f"(e + 1.0f));
    return fmaf(-2.0f, r, 1.0f);
}
// m-permutation: lane l owns m-pairs (64j+2l, 64j+2l+1); groups j01 / j23
// are 16B-contiguous at pos 4l and 128+4l.
__device__ __forceinline__ int permpos(int m) {
    int j = m >> 6, l = (m & 63) >> 1, e = m & 1;
    return 128 * (j >> 1) + 4 * l + 2 * (j & 1) + e;
}

// ---------------------------------------------------------------------------
__global__ void prep_kernel(const float* __restrict__ noise,
                            const int* __restrict__ nit_p,
                            float* __restrict__ out_u) {
    const int TOT = BB * HH * NUD;
    int idx = blockIdx.x * blockDim.x + threadIdx.x;
    if (idx >= TOT) return;
    int nit = *nit_p;
    float s = 0.f;
    for (int it = 0; it < nit - 1; ++it)
        s += noise[(size_t)it * TOT + idx];
    float u9 = 0.001f * s;
    g_u9[idx] = u9;
    int rem = idx % (HH * NUD);
    if (rem < NUD) {
        float u10 = u9 + 0.001f * noise[(size_t)(nit - 1) * TOT + idx];
        int b = idx / (HH * NUD);
        out_u[b * NUD + rem] = u10;
    }
}

// ---------------------------------------------------------------------------
// grid 128 x 384. Warps 0-7: rollout, 4 rows each (2 independent roll streams
// per SMSP cover each other's stalls). Warps 8-11: grad, 8 rows each.
// All m-indexed smem (W1 rows, t, gh, W2T m-dim) uses permpos() so every
// lane's data is 16B-contiguous -> LDS.128/STS.128 everywhere.
// ---------------------------------------------------------------------------
__global__ __launch_bounds__(NT, 1)
void mpc_kernel(const float* __restrict__ x0,
                const float* __restrict__ W1g,   // [80,256]
                const float* __restrict__ b1g,   // [256]
                const float* __restrict__ W2g,   // [256,64]
                float* __restrict__ out_xtraj,
                float* __restrict__ out_xpred,
                float* __restrict__ out_gx,
                float* __restrict__ out_gu) {
    extern __shared__ float smem[];
    float*  W1s  = smem + SM_W1;
    float*  W2Ts = smem + SM_W2T;
    float2* xd   = (float2*)(smem + SM_XD);
    float*  tall = smem + SM_TALL;
    float*  gall = smem + SM_GALL;

    const int tid = threadIdx.x;

    // ---- Stage weights (m-permuted) + c2 scratch (permuted, in tall) ----
    for (int idx = tid; idx < ZD * HIDD; idx += NT) {
        int i = idx >> 8, m = idx & 255;
        W1s[i * W1STRIDE + permpos(m)] = W1g[idx];
    }
    for (int idx = tid; idx < HIDD * NXD; idx += NT) {
        int m = idx >> 6, c = idx & 63;
        W2Ts[c * W2STRIDE + permpos(m)] = W2g[idx];
    }
    if (tid < HIDD) {
        int m = tid;
        float s = 0.f;
        #pragma unroll 8
        for (int j = 0; j < NXD; ++j) s += W2g[m * NXD + j];
        tall[permpos(m)] = 0.1f * s;   // c2 scratch (permuted)
    }
    __syncthreads();

    const int  w    = tid >> 5, lane = tid & 31;
    const bool roll = (w < 8);
    const int  m2   = 2 * lane;
    const int  urh  = lane >> 4, ui = lane & 15;
    const bool lo16 = (lane < 16);

    if (roll) {
        const int lr = w * 4;
        const int b0 = blockIdx.x * 32 + lr;

        // constants: b1 (global), c2 (permuted scratch)
        ull b1p[4], c2p[4], nc2p[4];
        #pragma unroll
        for (int j = 0; j < 4; ++j) {
            b1p[j] = *(const ull*)&b1g[64 * j + m2];
            F2U c;
            c.u = *(const ull*)&tall[128 * (j >> 1) + 4 * lane + 2 * (j & 1)];
            c2p[j] = c.u;
            F2U n; n.f.x = -c.f.x; n.f.y = -c.f.y;
            nc2p[j] = n.u;
        }
        __syncwarp();

        // init x into xd (dup) + x_traj[:,0,:]
        #pragma unroll
        for (int r = 0; r < 4; ++r) {
            int b = b0 + r;
            float xa = x0[b * NXD + lane];
            float xb = x0[b * NXD + 32 + lane];
            xd[(lr + r) * 64 + lane]      = make_float2(xa, xa);
            xd[(lr + r) * 64 + 32 + lane] = make_float2(xb, xb);
            size_t base = (size_t)b * (HH + 1) * NXD;
            out_xtraj[base + lane]      = xa;
            out_xtraj[base + 32 + lane] = xb;
        }
        float up[2];
        #pragma unroll
        for (int v = 0; v < 2; ++v)
            up[v] = g_u9[(size_t)(b0 + 2 * v + urh) * HH * NUD + ui];

        // u staging aliases this warp's own tall row lr (first 128 floats)
        float2* ud = (float2*)(tall + lr * 256);   // [4 rows][16] float2
        const ulonglong2* w2a = (const ulonglong2*)&W2Ts[lane * W2STRIDE];
        const ulonglong2* w2b = (const ulonglong2*)&W2Ts[(lane + 32) * W2STRIDE];

        for (int k = 0; k < HH; ++k) {
            // ---- stage controls (dup) ----
            #pragma unroll
            for (int v = 0; v < 2; ++v)
                ud[(2 * v + urh) * 16 + ui] = make_float2(up[v], up[v]);
            __syncwarp();
            if (k + 1 < HH) {
                #pragma unroll
                for (int v = 0; v < 2; ++v)
                    up[v] = g_u9[(size_t)(b0 + 2 * v + urh) * HH * NUD
                                 + (k + 1) * NUD + ui];
            }

            // ---- GEMV1: h = z @ W1 + b1 (permuted weights, LDS.128) ----
            ull h[4][4];
            #pragma unroll
            for (int r = 0; r < 4; ++r)
                #pragma unroll
                for (int j = 0; j < 4; ++j) h[r][j] = b1p[j];

            #pragma unroll 4
            for (int i = 0; i < NXD; i += 2) {       // x part
                const float* w0 = &W1s[i * W1STRIDE];
                const float* w1 = &W1s[(i + 1) * W1STRIDE];
                ulonglong2 wA = *(const ulonglong2*)&w0[4 * lane];
                ulonglong2 wB = *(const ulonglong2*)&w0[128 + 4 * lane];
                ulonglong2 wC = *(const ulonglong2*)&w1[4 * lane];
                ulonglong2 wD = *(const ulonglong2*)&w1[128 + 4 * lane];
                #pragma unroll
                for (int r = 0; r < 4; ++r) {
                    ulonglong2 zv = *(const ulonglong2*)&xd[(lr + r) * 64 + i];
                    h[r][0] = fma2(zv.x, wA.x, h[r][0]);
                    h[r][1] = fma2(zv.x, wA.y, h[r][1]);
                    h[r][2] = fma2(zv.x, wB.x, h[r][2]);
                    h[r][3] = fma2(zv.x, wB.y, h[r][3]);
                    h[r][0] = fma2(zv.y, wC.x, h[r][0]);
                    h[r][1] = fma2(zv.y, wC.y, h[r][1]);
                    h[r][2] = fma2(zv.y, wD.x, h[r][2]);
                    h[r][3] = fma2(zv.y, wD.y, h[r][3]);
                }
            }
            #pragma unroll 4
            for (int i = NXD; i < ZD; i += 2) {      // u part
                const float* w0 = &W1s[i * W1STRIDE];
                const float* w1 = &W1s[(i + 1) * W1STRIDE];
                ulonglong2 wA = *(const ulonglong2*)&w0[4 * lane];
                ulonglong2 wB = *(const ulonglong2*)&w0[128 + 4 * lane];
                ulonglong2 wC = *(const ulonglong2*)&w1[4 * lane];
                ulonglong2 wD = *(const ulonglong2*)&w1[128 + 4 * lane];
                #pragma unroll
                for (int r = 0; r < 4; ++r) {
                    ulonglong2 zv =
                        *(const ulonglong2*)&ud[r * 16 + (i - NXD)];
                    h[r][0] = fma2(zv.x, wA.x, h[r][0]);
                    h[r][1] = fma2(zv.x, wA.y, h[r][1]);
                    h[r][2] = fma2(zv.x, wB.x, h[r][2]);
                    h[r][3] = fma2(zv.x, wB.y, h[r][3]);
                    h[r][0] = fma2(zv.y, wC.x, h[r][0]);
                    h[r][1] = fma2(zv.y, wC.y, h[r][1]);
                    h[r][2] = fma2(zv.y, wD.x, h[r][2]);
                    h[r][3] = fma2(zv.y, wD.y, h[r][3]);
                }
            }

            __syncthreads();   // A: grad done reading gh(k-1)

            // ---- tanh; stage t and gh (permuted, STS.128) ----
            #pragma unroll
            for (int r = 0; r < 4; ++r) {
                ull tv[4], gv[4];
                #pragma unroll
                for (int j = 0; j < 4; ++j) {
                    F2U hv; hv.u = h[r][j];
                    F2U t;
                    t.f.x = tanhfast(hv.f.x);
                    t.f.y = tanhfast(hv.f.y);
                    tv[j] = t.u;
                    gv[j] = fma2(mul2(t.u, t.u), nc2p[j], c2p[j]);
                }
                int base = (lr + r) * 256;
                ulonglong2 s01, s23;
                s01.x = tv[0]; s01.y = tv[1];
                s23.x = tv[2]; s23.y = tv[3];
                *(ulonglong2*)&tall[base + 4 * lane]       = s01;
                *(ulonglong2*)&tall[base + 128 + 4 * lane] = s23;
                s01.x = gv[0]; s01.y = gv[1];
                s23.x = gv[2]; s23.y = gv[3];
                *(ulonglong2*)&gall[base + 4 * lane]       = s01;
                *(ulonglong2*)&gall[base + 128 + 4 * lane] = s23;
            }

            __syncthreads();   // B: t(k), gh(k) ready

            // ---- GEMV2: x_next = x + 0.1 * t @ W2 (permuted order) ----
            ull acc[4][2];
            #pragma unroll
            for (int r = 0; r < 4; ++r) { acc[r][0] = 0ull; acc[r][1] = 0ull; }
            #pragma unroll 4
            for (int q = 0; q < HIDD / 4; ++q) {
                ulonglong2 wa = w2a[q];
                ulonglong2 wb = w2b[q];
                #pragma unroll
                for (int r = 0; r < 4; ++r) {
                    ulonglong2 tv =
                        *(const ulonglong2*)&tall[(lr + r) * 256 + 4 * q];
                    acc[r][0] = fma2(tv.x, wa.x, acc[r][0]);
                    acc[r][0] = fma2(tv.y, wa.y, acc[r][0]);
                    acc[r][1] = fma2(tv.x, wb.x, acc[r][1]);
                    acc[r][1] = fma2(tv.y, wb.y, acc[r][1]);
                }
            }
            #pragma unroll
            for (int r = 0; r < 4; ++r) {
                int b = b0 + r;
                F2U a0; a0.u = acc[r][0];
                F2U a1; a1.u = acc[r][1];
                float xn0 = xd[(lr + r) * 64 + lane].x
                            + 0.1f * (a0.f.x + a0.f.y);
                float xn1 = xd[(lr + r) * 64 + 32 + lane].x
                            + 0.1f * (a1.f.x + a1.f.y);
                size_t base_t = (size_t)b * (HH + 1) * NXD
                                + (size_t)(k + 1) * NXD;
                size_t base_p = (size_t)b * HH * NXD + (size_t)k * NXD;
                out_xtraj[base_t + lane]      = xn0;
                out_xtraj[base_t + 32 + lane] = xn1;
                out_xpred[base_p + lane]      = xn0;
                out_xpred[base_p + 32 + lane] = xn1;
                xd[(lr + r) * 64 + lane]      = make_float2(xn0, xn0);
                xd[(lr + r) * 64 + 32 + lane] = make_float2(xn1, xn1);
            }
            __syncwarp();
        }
    } else {
        // ---------------- grad warps: 8 rows each ----------------
        const int gw  = w - 8;
        const int lrg = gw * 8;
        const int bg  = blockIdx.x * 32 + lrg;

        const ulonglong2* wia = (const ulonglong2*)&W1s[lane * W1STRIDE];
        const ulonglong2* wib = (const ulonglong2*)&W1s[(32 + lane) * W1STRIDE];
        const ulonglong2* wic = (const ulonglong2*)&W1s[(64 + ui) * W1STRIDE];
        const float* gb_ = gall + lrg * 256;

        for (int k = 0; k < HH; ++k) {
            __syncthreads();   // A
            __syncthreads();   // B: gh(k) ready

            ull ga[8], gb8[8], gc4[4];
            #pragma unroll
            for (int r = 0; r < 8; ++r) { ga[r] = 0ull; gb8[r] = 0ull; }
            #pragma unroll
            for (int r = 0; r < 4; ++r) gc4[r] = 0ull;

            #pragma unroll 4
            for (int q = 0; q < HIDD / 4; ++q) {
                ulonglong2 wa = wia[q];
                ulonglong2 wb = wib[q];
                ulonglong2 wc = wic[q];
                ull gl[8][2];
                #pragma unroll
                for (int r = 0; r < 8; ++r) {
                    ulonglong2 gv = *(const ulonglong2*)&gb_[r * 256 + 4 * q];
                    gl[r][0] = gv.x; gl[r][1] = gv.y;
                    ga[r]  = fma2(gv.x, wa.x, ga[r]);
                    ga[r]  = fma2(gv.y, wa.y, ga[r]);
                    gb8[r] = fma2(gv.x, wb.x, gb8[r]);
                    gb8[r] = fma2(gv.y, wb.y, gb8[r]);
                }
                #pragma unroll
                for (int r = 0; r < 4; ++r) {
                    ull s0 = lo16 ? gl[r][0] : gl[r + 4][0];
                    ull s1 = lo16 ? gl[r][1] : gl[r + 4][1];
                    gc4[r] = fma2(s0, wc.x, gc4[r]);
                    gc4[r] = fma2(s1, wc.y, gc4[r]);
                }
            }
            #pragma unroll
            for (int r = 0; r < 8; ++r) {
                int b = bg + r;
                F2U va; va.u = ga[r];
                F2U vb; vb.u = gb8[r];
                size_t base_gx = (size_t)b * HH * NXD + (size_t)k * NXD;
                out_gx[base_gx + lane]      = 1.f + va.f.x + va.f.y;
                out_gx[base_gx + 32 + lane] = 1.f + vb.f.x + vb.f.y;
            }
            #pragma unroll
            for (int r = 0; r < 4; ++r) {
                int b = bg + r + (lo16 ? 0 : 4);
                F2U vc; vc.u = gc4[r];
                out_gu[(size_t)b * HH * NUD + (size_t)k * NUD + ui] =
                    vc.f.x + vc.f.y;
            }
        }
    }
}

// ---------------------------------------------------------------------------
extern "C" void kernel_launch(void* const* d_in, const int* in_sizes, int n_in,
                              void* d_out, int out_size) {
    const float* x0    = (const float*)d_in[0];
    const float* W1    = (const float*)d_in[2];
    const float* b1    = (const float*)d_in[3];
    const float* W2    = (const float*)d_in[4];
    const float* noise = (const float*)d_in[5];
    const int*   nit   = (const int*)d_in[6];

    float* out = (float*)d_out;
    float* out_u     = out + OFF_U;
    float* out_xtraj = out + OFF_XTRAJ;
    float* out_xpred = out + OFF_XPRED;
    float* out_gx    = out + OFF_GX;
    float* out_gu    = out + OFF_GU;

    {
        int tot = BB * HH * NUD;
        prep_kernel<<<(tot + 255) / 256, 256>>>(noise, nit, out_u);
    }

    const size_t smem_bytes = (size_t)SM_TOTAL_F * sizeof(float);  // 231,680
    cudaFuncSetAttribute(mpc_kernel,
                         cudaFuncAttributeMaxDynamicSharedMemorySize,
                         (int)smem_bytes);
    mpc_kernel<<<BB / 32, NT, smem_bytes>>>(x0, W1, b1, W2,
                                            out_xtraj, out_xpred,
                                            out_gx, out_gu);
}